// round 3
// baseline (speedup 1.0000x reference)
#include <cuda_runtime.h>
#include <cuda_bf16.h>
#include <cstddef>

// Problem constants
#define H_DIM 1024
#define I_DIM 1024
#define C_DIM 64

// Tile config: 128x128 block tile, K-tile 16, 256 threads, 8x8 per-thread micro-tile
#define BM 128
#define BN 128
#define BK 16
#define TM 8
#define TN 8

// 256 MB ping-pong scratch buffers (C*H*I floats each)
__device__ float g_buf1[(size_t)C_DIM * H_DIM * I_DIM];
__device__ float g_buf2[(size_t)C_DIM * H_DIM * I_DIM];

__device__ __forceinline__ float actf(float x) {
    // (|x+1| - |x-1|)/2 == clamp(x, -1, 1)
    return fminf(fmaxf(x, -1.0f), 1.0f);
}

// ---------------------------------------------------------------------------
// NN GEMM: Out[c,h,i] = act( sum_k A[h,k] * B3[c,k,i] )
// MODE 0: A = Wp (tril + diag clamp + Wdiag fused at load),
//         B3 = x with act(p_mask) fused at load, triangular k-tile skip.
// MODE 1: A = Wzp plain, B3 = p_out buffer.
// ---------------------------------------------------------------------------
template <int MODE>
__global__ __launch_bounds__(256, 2)
void gemm_nn_kernel(const float* __restrict__ A,
                    const float* __restrict__ B3,
                    const float* __restrict__ PM,
                    const float* __restrict__ Wdiag,
                    float* __restrict__ Out)
{
    __shared__ float As[BK][BM];
    __shared__ float Bs[BK][BN];

    const int tid = threadIdx.x;
    const int m0 = blockIdx.y * BM;
    const int n0 = blockIdx.x * BN;
    const int c  = blockIdx.z;
    const size_t chanOff = (size_t)c * H_DIM * I_DIM;

    // Triangular skip for MODE 0: Wp_eff is lower-triangular -> only need k <= m0+BM-1
    const int kTiles = (MODE == 0) ? ((blockIdx.y + 1) * BM) / BK : (H_DIM / BK);

    const int r0 = (tid / 16) * TM;   // row offset within tile
    const int c0 = (tid % 16) * TN;   // col offset within tile

    float acc[TM][TN];
#pragma unroll
    for (int i = 0; i < TM; ++i)
#pragma unroll
        for (int j = 0; j < TN; ++j) acc[i][j] = 0.0f;

    for (int kt = 0; kt < kTiles; ++kt) {
        const int k0 = kt * BK;

        // --- Load A tile (BM x BK), store transposed As[k][m] ---
#pragma unroll
        for (int l = 0; l < 2; ++l) {
            const int f = tid + l * 256;       // 0..511 float4 slots
            const int row  = f >> 2;           // 0..127
            const int col4 = f & 3;            // 0..3
            float4 v = *(const float4*)&A[(size_t)(m0 + row) * H_DIM + k0 + col4 * 4];
            float vv[4] = {v.x, v.y, v.z, v.w};
#pragma unroll
            for (int e = 0; e < 4; ++e) {
                float val = vv[e];
                if (MODE == 0) {
                    const int k = k0 + col4 * 4 + e;
                    const int h = m0 + row;
                    if (k > h) {
                        val = 0.0f;
                    } else if (k == h) {
                        val = fminf(fmaxf(val, 0.0f), 1.0f) + Wdiag[h];
                    }
                }
                As[col4 * 4 + e][row] = val;
            }
        }

        // --- Load B tile (BK x BN) ---
#pragma unroll
        for (int l = 0; l < 2; ++l) {
            const int f = tid + l * 256;
            const int row  = f >> 5;           // 0..15
            const int col4 = f & 31;           // 0..31
            const size_t gidx = chanOff + (size_t)(k0 + row) * I_DIM + n0 + col4 * 4;
            float4 v = *(const float4*)&B3[gidx];
            if (MODE == 0) {
                const float4 pm = *(const float4*)&PM[(size_t)(k0 + row) * I_DIM + n0 + col4 * 4];
                v.x *= actf(pm.x);
                v.y *= actf(pm.y);
                v.z *= actf(pm.z);
                v.w *= actf(pm.w);
            }
            *(float4*)&Bs[row][col4 * 4] = v;
        }

        __syncthreads();

#pragma unroll
        for (int kk = 0; kk < BK; ++kk) {
            float a[TM], b[TN];
#pragma unroll
            for (int i = 0; i < TM; ++i) a[i] = As[kk][r0 + i];
#pragma unroll
            for (int j = 0; j < TN; ++j) b[j] = Bs[kk][c0 + j];
#pragma unroll
            for (int i = 0; i < TM; ++i)
#pragma unroll
                for (int j = 0; j < TN; ++j) acc[i][j] = fmaf(a[i], b[j], acc[i][j]);
        }

        __syncthreads();
    }

    // --- Epilogue: act() and store ---
#pragma unroll
    for (int i = 0; i < TM; ++i) {
        const size_t base = chanOff + (size_t)(m0 + r0 + i) * I_DIM + n0 + c0;
#pragma unroll
        for (int j = 0; j < TN; j += 4) {
            float4 v;
            v.x = actf(acc[i][j + 0]);
            v.y = actf(acc[i][j + 1]);
            v.z = actf(acc[i][j + 2]);
            v.w = actf(acc[i][j + 3]);
            *(float4*)&Out[base + j] = v;
        }
    }
}

// ---------------------------------------------------------------------------
// NT GEMM: Out[c,h,j] = act( sum_i In[c,h,i] * W[j,i] + bias[j] ) (+ Padd if FINAL)
// ---------------------------------------------------------------------------
template <int FINAL>
__global__ __launch_bounds__(256, 2)
void gemm_nt_kernel(const float* __restrict__ In,
                    const float* __restrict__ W,
                    const float* __restrict__ bias,
                    const float* __restrict__ Padd,
                    float* __restrict__ Out)
{
    __shared__ float As[BK][BM];
    __shared__ float Bs[BK][BN];

    const int tid = threadIdx.x;
    const int m0 = blockIdx.y * BM;
    const int n0 = blockIdx.x * BN;
    const int c  = blockIdx.z;
    const size_t chanOff = (size_t)c * H_DIM * I_DIM;

    const int kTiles = I_DIM / BK;

    const int r0 = (tid / 16) * TM;
    const int c0 = (tid % 16) * TN;

    float acc[TM][TN];
#pragma unroll
    for (int i = 0; i < TM; ++i)
#pragma unroll
        for (int j = 0; j < TN; ++j) acc[i][j] = 0.0f;

    for (int kt = 0; kt < kTiles; ++kt) {
        const int k0 = kt * BK;

        // --- Load In tile (BM rows x BK cols), store transposed As[k][m] ---
#pragma unroll
        for (int l = 0; l < 2; ++l) {
            const int f = tid + l * 256;
            const int row  = f >> 2;   // 0..127 (h)
            const int col4 = f & 3;    // 0..3
            float4 v = *(const float4*)&In[chanOff + (size_t)(m0 + row) * I_DIM + k0 + col4 * 4];
            As[col4 * 4 + 0][row] = v.x;
            As[col4 * 4 + 1][row] = v.y;
            As[col4 * 4 + 2][row] = v.z;
            As[col4 * 4 + 3][row] = v.w;
        }

        // --- Load W tile (BN rows x BK cols), store transposed Bs[k][n] ---
#pragma unroll
        for (int l = 0; l < 2; ++l) {
            const int f = tid + l * 256;
            const int row  = f >> 2;   // 0..127 (j = output col)
            const int col4 = f & 3;    // 0..3
            float4 v = *(const float4*)&W[(size_t)(n0 + row) * I_DIM + k0 + col4 * 4];
            Bs[col4 * 4 + 0][row] = v.x;
            Bs[col4 * 4 + 1][row] = v.y;
            Bs[col4 * 4 + 2][row] = v.z;
            Bs[col4 * 4 + 3][row] = v.w;
        }

        __syncthreads();

#pragma unroll
        for (int kk = 0; kk < BK; ++kk) {
            float a[TM], b[TN];
#pragma unroll
            for (int i = 0; i < TM; ++i) a[i] = As[kk][r0 + i];
#pragma unroll
            for (int j = 0; j < TN; ++j) b[j] = Bs[kk][c0 + j];
#pragma unroll
            for (int i = 0; i < TM; ++i)
#pragma unroll
                for (int j = 0; j < TN; ++j) acc[i][j] = fmaf(a[i], b[j], acc[i][j]);
        }

        __syncthreads();
    }

    // --- Epilogue: bias + act (+ residual add for FINAL) ---
    float bj[TN];
#pragma unroll
    for (int j = 0; j < TN; ++j) bj[j] = bias[n0 + c0 + j];

#pragma unroll
    for (int i = 0; i < TM; ++i) {
        const size_t base = chanOff + (size_t)(m0 + r0 + i) * I_DIM + n0 + c0;
#pragma unroll
        for (int j = 0; j < TN; j += 4) {
            float4 v;
            v.x = actf(acc[i][j + 0] + bj[j + 0]);
            v.y = actf(acc[i][j + 1] + bj[j + 1]);
            v.z = actf(acc[i][j + 2] + bj[j + 2]);
            v.w = actf(acc[i][j + 3] + bj[j + 3]);
            if (FINAL) {
                const float4 p = *(const float4*)&Padd[base + j];
                v.x += p.x; v.y += p.y; v.z += p.z; v.w += p.w;
            }
            *(float4*)&Out[base + j] = v;
        }
    }
}

extern "C" void kernel_launch(void* const* d_in, const int* in_sizes, int n_in,
                              void* d_out, int out_size)
{
    (void)in_sizes; (void)n_in; (void)out_size;

    const float* x       = (const float*)d_in[0];  // (C,H,I)
    const float* p_mask  = (const float*)d_in[1];  // (H,I)
    const float* Wp      = (const float*)d_in[2];  // (H,H)
    const float* Wp_diag = (const float*)d_in[3];  // (H,)
    const float* Wzp     = (const float*)d_in[4];  // (H,H)
    const float* p_lin_w = (const float*)d_in[5];  // (I,I)
    const float* p_lin_b = (const float*)d_in[6];  // (I,)
    const float* z_lin_w = (const float*)d_in[7];  // (I,I)
    const float* z_lin_b = (const float*)d_in[8];  // (I,)
    float* out = (float*)d_out;

    float* buf1 = nullptr;
    float* buf2 = nullptr;
    cudaGetSymbolAddress((void**)&buf1, g_buf1);
    cudaGetSymbolAddress((void**)&buf2, g_buf2);

    dim3 grid(I_DIM / BN, H_DIM / BM, C_DIM);
    dim3 block(256);

    // Stage 1: buf1 = act( Wp_eff @ (x * act(p_mask)) )   [triangular skip]
    gemm_nn_kernel<0><<<grid, block>>>(Wp, x, p_mask, Wp_diag, buf1);
    // Stage 2: buf2 = act( buf1 @ p_lin_w^T + p_lin_b )   (= p_out)
    gemm_nt_kernel<0><<<grid, block>>>(buf1, p_lin_w, p_lin_b, nullptr, buf2);
    // Stage 3: buf1 = act( Wzp @ buf2 )
    gemm_nn_kernel<1><<<grid, block>>>(Wzp, buf2, nullptr, nullptr, buf1);
    // Stage 4: out = buf2 + act( buf1 @ z_lin_w^T + z_lin_b )
    gemm_nt_kernel<1><<<grid, block>>>(buf1, z_lin_w, z_lin_b, buf2, out);
}

// round 10
// speedup vs baseline: 2.0846x; 2.0846x over previous
#include <cuda_runtime.h>
#include <cuda_bf16.h>
#include <cstdint>
#include <cstddef>

#define H_DIM 1024
#define I_DIM 1024
#define C_DIM 64

// ---------------------------------------------------------------------------
// Static scratch (module-load allocated; no runtime allocation).
// Explicit 256B alignment — the GEMM uses 16B vector accesses
// (cp.async / uint4) relative to these bases.
// ---------------------------------------------------------------------------
#define ACT_ELEMS ((size_t)C_DIM * H_DIM * I_DIM)   // 64Mi elements
__device__ __align__(256) __nv_bfloat16 g_xth[ACT_ELEMS];   // x*act(pm)^T hi (later z_act)
__device__ __align__(256) __nv_bfloat16 g_xtl[ACT_ELEMS];   // ... lo
__device__ __align__(256) __nv_bfloat16 g_b1h[ACT_ELEMS];   // stage1 out hi (later p_out^T)
__device__ __align__(256) __nv_bfloat16 g_b1l[ACT_ELEMS];
__device__ __align__(256) __nv_bfloat16 g_ph[ACT_ELEMS];    // p_out hi
__device__ __align__(256) __nv_bfloat16 g_pl[ACT_ELEMS];
__device__ __align__(256) __nv_bfloat16 g_wph[H_DIM * H_DIM];
__device__ __align__(256) __nv_bfloat16 g_wpl[H_DIM * H_DIM];
__device__ __align__(256) __nv_bfloat16 g_plh[I_DIM * I_DIM];
__device__ __align__(256) __nv_bfloat16 g_pll[I_DIM * I_DIM];
__device__ __align__(256) __nv_bfloat16 g_wzh[H_DIM * H_DIM];
__device__ __align__(256) __nv_bfloat16 g_wzl[H_DIM * H_DIM];
__device__ __align__(256) __nv_bfloat16 g_zlh[I_DIM * I_DIM];
__device__ __align__(256) __nv_bfloat16 g_zll[I_DIM * I_DIM];

__device__ __forceinline__ float actf(float x) { return fminf(fmaxf(x, -1.0f), 1.0f); }

__device__ __forceinline__ void split_bf16(float v, __nv_bfloat16& hi, __nv_bfloat16& lo) {
    hi = __float2bfloat16(v);
    lo = __float2bfloat16(v - __bfloat162float(hi));
}

// ---------------------------------------------------------------------------
// Elementwise prep kernels
// ---------------------------------------------------------------------------
__global__ void prep_wp_kernel(const float* __restrict__ Wp, const float* __restrict__ Wd,
                               __nv_bfloat16* __restrict__ Oh, __nv_bfloat16* __restrict__ Ol) {
    const int h = blockIdx.x;
    const float dv = Wd[h];
#pragma unroll
    for (int j = 0; j < 4; ++j) {
        const int k = threadIdx.x + j * 256;
        float v = Wp[h * H_DIM + k];
        if (k > h) v = 0.0f;
        else if (k == h) v = fminf(fmaxf(v, 0.0f), 1.0f) + dv;
        __nv_bfloat16 hi, lo; split_bf16(v, hi, lo);
        Oh[h * H_DIM + k] = hi;
        Ol[h * H_DIM + k] = lo;
    }
}

__global__ void conv_mat_kernel(const float* __restrict__ W,
                                __nv_bfloat16* __restrict__ Oh, __nv_bfloat16* __restrict__ Ol) {
    const int i4 = (blockIdx.x * 256 + threadIdx.x) * 4;
    const float4 v = *(const float4*)(W + i4);
    const float vv[4] = {v.x, v.y, v.z, v.w};
    union { uint2 u; __nv_bfloat16 b[4]; } ph, pl;
#pragma unroll
    for (int e = 0; e < 4; ++e) { split_bf16(vv[e], ph.b[e], pl.b[e]); }
    *(uint2*)(Oh + i4) = ph.u;
    *(uint2*)(Ol + i4) = pl.u;
}

// XT[c,i,k] = x[c,k,i] * act(pm[k,i]) -> hi/lo
__global__ void convT_x_kernel(const float* __restrict__ x, const float* __restrict__ pm,
                               __nv_bfloat16* __restrict__ Th, __nv_bfloat16* __restrict__ Tl) {
    __shared__ float t[32][33];
    const int i0 = blockIdx.x * 32, k0 = blockIdx.y * 32;
    const size_t cOff = (size_t)blockIdx.z << 20;
    const int tx = threadIdx.x, ty = threadIdx.y;
#pragma unroll
    for (int r = 0; r < 4; ++r) {
        const int k = k0 + ty + r * 8;
        const float m = actf(pm[(size_t)k * I_DIM + i0 + tx]);
        t[ty + r * 8][tx] = x[cOff + (size_t)k * I_DIM + i0 + tx] * m;
    }
    __syncthreads();
#pragma unroll
    for (int r = 0; r < 4; ++r) {
        const int i = i0 + ty + r * 8;
        const float v = t[tx][ty + r * 8];
        __nv_bfloat16 hi, lo; split_bf16(v, hi, lo);
        Th[cOff + (size_t)i * H_DIM + k0 + tx] = hi;
        Tl[cOff + (size_t)i * H_DIM + k0 + tx] = lo;
    }
}

// PT[c,i,h] = P[c,h,i]  (bf16 hi/lo pair transpose)
__global__ void transP_kernel(const __nv_bfloat16* __restrict__ Ph, const __nv_bfloat16* __restrict__ Pl,
                              __nv_bfloat16* __restrict__ Th, __nv_bfloat16* __restrict__ Tl) {
    __shared__ __nv_bfloat16 th[32][34], tl[32][34];
    const int i0 = blockIdx.x * 32, h0 = blockIdx.y * 32;
    const size_t cOff = (size_t)blockIdx.z << 20;
    const int tx = threadIdx.x, ty = threadIdx.y;
#pragma unroll
    for (int r = 0; r < 4; ++r) {
        const int h = h0 + ty + r * 8;
        th[ty + r * 8][tx] = Ph[cOff + (size_t)h * I_DIM + i0 + tx];
        tl[ty + r * 8][tx] = Pl[cOff + (size_t)h * I_DIM + i0 + tx];
    }
    __syncthreads();
#pragma unroll
    for (int r = 0; r < 4; ++r) {
        const int i = i0 + ty + r * 8;
        Th[cOff + (size_t)i * H_DIM + h0 + tx] = th[tx][ty + r * 8];
        Tl[cOff + (size_t)i * H_DIM + h0 + tx] = tl[tx][ty + r * 8];
    }
}

// ---------------------------------------------------------------------------
// mma.sync helpers (base ISA, valid on target sm_103)
// ---------------------------------------------------------------------------
__device__ __forceinline__ void mma16816(float* d, const uint32_t* a, const uint32_t* b) {
    asm volatile(
        "mma.sync.aligned.m16n8k16.row.col.f32.bf16.bf16.f32 "
        "{%0,%1,%2,%3}, {%4,%5,%6,%7}, {%8,%9}, {%0,%1,%2,%3};"
        : "+f"(d[0]), "+f"(d[1]), "+f"(d[2]), "+f"(d[3])
        : "r"(a[0]), "r"(a[1]), "r"(a[2]), "r"(a[3]), "r"(b[0]), "r"(b[1]));
}
__device__ __forceinline__ void cp16(uint32_t dst, const void* src) {
    asm volatile("cp.async.cg.shared.global [%0], [%1], 16;" :: "r"(dst), "l"(src) : "memory");
}
__device__ __forceinline__ uint32_t smem_u32(const void* p) {
    uint32_t a;
    asm("{ .reg .u64 t; cvta.to.shared.u64 t, %1; cvt.u32.u64 %0, t; }" : "=r"(a) : "l"(p));
    return a;
}

// ---------------------------------------------------------------------------
// GEMM: D[m,n] = sum_k A[m,k]*B[n,k] (both K-contiguous), 3-term bf16 split,
// fp32 accum via mma.sync m16n8k16. Tile 128x128, BK=32, 8 warps (64x32 each),
// cp.async double-buffered. Padded smem rows (80B) -> conflict-free LDS frags.
// APC/BPC: per-channel operand. TRI: triangular k-skip (stage 1).
// EPI: 0 = act -> hi/lo; 1 = act(x+bias) -> hi/lo; 2 = act(x+bias)+res -> f32.
// ---------------------------------------------------------------------------
#define TILE_B 10240        // 128 rows * 80 bytes
#define BUF_B  (4 * TILE_B) // Ah, Al, Bh, Bl

template <int APC, int BPC, int TRI, int EPI>
__global__ __launch_bounds__(256, 1)
void gemm_mma(const __nv_bfloat16* __restrict__ Ah, const __nv_bfloat16* __restrict__ Al,
              const __nv_bfloat16* __restrict__ Bh, const __nv_bfloat16* __restrict__ Bl,
              const float* __restrict__ bias,
              const __nv_bfloat16* __restrict__ Rh, const __nv_bfloat16* __restrict__ Rl,
              __nv_bfloat16* __restrict__ Oh, __nv_bfloat16* __restrict__ Ol,
              float* __restrict__ Of)
{
    extern __shared__ char smem[];
    const uint32_t sb = smem_u32(smem);
    const int tid = threadIdx.x;
    const int wid = tid >> 5;
    const int lane = tid & 31;
    const int gID = lane >> 2;      // 0..7
    const int tg  = lane & 3;       // 0..3
    const int warp_m = wid & 1;     // 2 warps over M
    const int warp_n = wid >> 1;    // 4 warps over N
    const int n0 = blockIdx.x * 128;
    const int m0 = blockIdx.y * 128;
    const size_t cOff = (size_t)blockIdx.z << 20;

    const int nch = TRI ? (blockIdx.y + 1) * 4 : 32;   // BK=32 chunks

    const __nv_bfloat16* src[4];
    src[0] = Ah + (APC ? cOff : 0) + (size_t)m0 * 1024;
    src[1] = Al + (APC ? cOff : 0) + (size_t)m0 * 1024;
    src[2] = Bh + (BPC ? cOff : 0) + (size_t)n0 * 1024;
    src[3] = Bl + (BPC ? cOff : 0) + (size_t)n0 * 1024;

    // cp.async issue of one 32-wide K chunk into buffer b
    auto issue = [&](int kc, int b) {
#pragma unroll
        for (int t = 0; t < 4; ++t) {
#pragma unroll
            for (int i = 0; i < 2; ++i) {
                const int u = tid + i * 256;        // 0..511 16B units
                const int row = u >> 2;             // 0..127
                const int c16 = u & 3;              // 0..3
                cp16(sb + b * BUF_B + t * TILE_B + row * 80 + c16 * 16,
                     src[t] + (size_t)row * 1024 + kc * 32 + c16 * 8);
            }
        }
        asm volatile("cp.async.commit_group;" ::: "memory");
    };

    float acc[4][4][4];
#pragma unroll
    for (int mt = 0; mt < 4; ++mt)
#pragma unroll
        for (int nt = 0; nt < 4; ++nt)
#pragma unroll
            for (int r = 0; r < 4; ++r) acc[mt][nt][r] = 0.0f;

    issue(0, 0);

    for (int kc = 0; kc < nch; ++kc) {
        const int b = kc & 1;
        if (kc + 1 < nch) {
            issue(kc + 1, b ^ 1);
            asm volatile("cp.async.wait_group 1;" ::: "memory");
        } else {
            asm volatile("cp.async.wait_group 0;" ::: "memory");
        }
        __syncthreads();

        const char* Abh = smem + b * BUF_B;
        const char* Abl = Abh + TILE_B;
        const char* Bbh = Abh + 2 * TILE_B;
        const char* Bbl = Abh + 3 * TILE_B;

#pragma unroll
        for (int ks = 0; ks < 2; ++ks) {
            const int ko = ks * 32 + tg * 4;
            uint32_t ah[4][4], al[4][4], bhf[4][2], blf[4][2];
#pragma unroll
            for (int mt = 0; mt < 4; ++mt) {
                const char* pa = Abh + (warp_m * 64 + mt * 16 + gID) * 80 + ko;
                ah[mt][0] = *(const uint32_t*)(pa);
                ah[mt][1] = *(const uint32_t*)(pa + 640);
                ah[mt][2] = *(const uint32_t*)(pa + 16);
                ah[mt][3] = *(const uint32_t*)(pa + 656);
                const char* pl_ = Abl + (warp_m * 64 + mt * 16 + gID) * 80 + ko;
                al[mt][0] = *(const uint32_t*)(pl_);
                al[mt][1] = *(const uint32_t*)(pl_ + 640);
                al[mt][2] = *(const uint32_t*)(pl_ + 16);
                al[mt][3] = *(const uint32_t*)(pl_ + 656);
            }
#pragma unroll
            for (int nt = 0; nt < 4; ++nt) {
                const char* pb = Bbh + (warp_n * 32 + nt * 8 + gID) * 80 + ko;
                bhf[nt][0] = *(const uint32_t*)(pb);
                bhf[nt][1] = *(const uint32_t*)(pb + 16);
                const char* pq = Bbl + (warp_n * 32 + nt * 8 + gID) * 80 + ko;
                blf[nt][0] = *(const uint32_t*)(pq);
                blf[nt][1] = *(const uint32_t*)(pq + 16);
            }
#pragma unroll
            for (int mt = 0; mt < 4; ++mt)
#pragma unroll
                for (int nt = 0; nt < 4; ++nt) {
                    mma16816(acc[mt][nt], ah[mt], bhf[nt]);
                    mma16816(acc[mt][nt], ah[mt], blf[nt]);
                    mma16816(acc[mt][nt], al[mt], bhf[nt]);
                }
        }
        __syncthreads();
    }

    // --- Epilogue: stage fp32 tile in smem (pitch 129), then coalesced stores ---
    float* F = (float*)smem;
#pragma unroll
    for (int mt = 0; mt < 4; ++mt)
#pragma unroll
        for (int nt = 0; nt < 4; ++nt)
#pragma unroll
            for (int r = 0; r < 4; ++r) {
                const int rr = warp_m * 64 + mt * 16 + gID + (r >= 2 ? 8 : 0);
                const int cc = warp_n * 32 + nt * 8 + 2 * tg + (r & 1);
                F[rr * 129 + cc] = acc[mt][nt][r];
            }
    __syncthreads();

    {
        const int r  = tid >> 1;
        const int hf = tid & 1;
        const float* Frow = F + r * 129 + hf * 64;
        const size_t ob = cOff + (size_t)(m0 + r) * 1024 + n0 + hf * 64;
        const int jb = n0 + hf * 64;

        float bj[64];
        if (EPI >= 1) {
#pragma unroll
            for (int e4 = 0; e4 < 16; ++e4) {
                const float4 bv = *(const float4*)(bias + jb + e4 * 4);
                bj[e4 * 4 + 0] = bv.x; bj[e4 * 4 + 1] = bv.y;
                bj[e4 * 4 + 2] = bv.z; bj[e4 * 4 + 3] = bv.w;
            }
        }

#pragma unroll
        for (int g = 0; g < 8; ++g) {
            float v[8];
#pragma unroll
            for (int e = 0; e < 8; ++e) {
                float t = Frow[g * 8 + e];
                if (EPI >= 1) t += bj[g * 8 + e];
                v[e] = actf(t);
            }
            if (EPI == 2) {
                union { uint4 u; __nv_bfloat16 b[8]; } rh, rl;
                rh.u = *(const uint4*)(Rh + ob + g * 8);
                rl.u = *(const uint4*)(Rl + ob + g * 8);
                float4 o0, o1;
                o0.x = v[0] + __bfloat162float(rh.b[0]) + __bfloat162float(rl.b[0]);
                o0.y = v[1] + __bfloat162float(rh.b[1]) + __bfloat162float(rl.b[1]);
                o0.z = v[2] + __bfloat162float(rh.b[2]) + __bfloat162float(rl.b[2]);
                o0.w = v[3] + __bfloat162float(rh.b[3]) + __bfloat162float(rl.b[3]);
                o1.x = v[4] + __bfloat162float(rh.b[4]) + __bfloat162float(rl.b[4]);
                o1.y = v[5] + __bfloat162float(rh.b[5]) + __bfloat162float(rl.b[5]);
                o1.z = v[6] + __bfloat162float(rh.b[6]) + __bfloat162float(rl.b[6]);
                o1.w = v[7] + __bfloat162float(rh.b[7]) + __bfloat162float(rl.b[7]);
                *(float4*)(Of + ob + g * 8)     = o0;
                *(float4*)(Of + ob + g * 8 + 4) = o1;
            } else {
                union { uint4 u; __nv_bfloat16 b[8]; } oh_, ol_;
#pragma unroll
                for (int e = 0; e < 8; ++e) split_bf16(v[e], oh_.b[e], ol_.b[e]);
                *(uint4*)(Oh + ob + g * 8) = oh_.u;
                *(uint4*)(Ol + ob + g * 8) = ol_.u;
            }
        }
    }
}

// ---------------------------------------------------------------------------
// Host launcher
// ---------------------------------------------------------------------------
extern "C" void kernel_launch(void* const* d_in, const int* in_sizes, int n_in,
                              void* d_out, int out_size)
{
    (void)in_sizes; (void)n_in; (void)out_size;
    const float* x       = (const float*)d_in[0];
    const float* p_mask  = (const float*)d_in[1];
    const float* Wp      = (const float*)d_in[2];
    const float* Wp_diag = (const float*)d_in[3];
    const float* Wzp     = (const float*)d_in[4];
    const float* p_lin_w = (const float*)d_in[5];
    const float* p_lin_b = (const float*)d_in[6];
    const float* z_lin_w = (const float*)d_in[7];
    const float* z_lin_b = (const float*)d_in[8];
    float* out = (float*)d_out;

    __nv_bfloat16 *xth, *xtl, *b1h, *b1l, *ph, *pl;
    __nv_bfloat16 *wph, *wpl, *plh, *pll, *wzh, *wzl, *zlh, *zll;
    cudaGetSymbolAddress((void**)&xth, g_xth); cudaGetSymbolAddress((void**)&xtl, g_xtl);
    cudaGetSymbolAddress((void**)&b1h, g_b1h); cudaGetSymbolAddress((void**)&b1l, g_b1l);
    cudaGetSymbolAddress((void**)&ph,  g_ph);  cudaGetSymbolAddress((void**)&pl,  g_pl);
    cudaGetSymbolAddress((void**)&wph, g_wph); cudaGetSymbolAddress((void**)&wpl, g_wpl);
    cudaGetSymbolAddress((void**)&plh, g_plh); cudaGetSymbolAddress((void**)&pll, g_pll);
    cudaGetSymbolAddress((void**)&wzh, g_wzh); cudaGetSymbolAddress((void**)&wzl, g_wzl);
    cudaGetSymbolAddress((void**)&zlh, g_zlh); cudaGetSymbolAddress((void**)&zll, g_zll);

    // smem: max(2 double buffers = 81920, epilogue staging 128*129*4 = 66048)
    const int SMEM = 2 * BUF_B;  // 81920
    cudaFuncSetAttribute(gemm_mma<0,1,1,0>, cudaFuncAttributeMaxDynamicSharedMemorySize, SMEM);
    cudaFuncSetAttribute(gemm_mma<1,0,0,1>, cudaFuncAttributeMaxDynamicSharedMemorySize, SMEM);
    cudaFuncSetAttribute(gemm_mma<0,1,0,0>, cudaFuncAttributeMaxDynamicSharedMemorySize, SMEM);
    cudaFuncSetAttribute(gemm_mma<1,0,0,2>, cudaFuncAttributeMaxDynamicSharedMemorySize, SMEM);

    // Prep: weight splits + masked/transposed x
    prep_wp_kernel<<<H_DIM, 256>>>(Wp, Wp_diag, wph, wpl);
    conv_mat_kernel<<<1024, 256>>>(p_lin_w, plh, pll);
    conv_mat_kernel<<<1024, 256>>>(Wzp, wzh, wzl);
    conv_mat_kernel<<<1024, 256>>>(z_lin_w, zlh, zll);
    convT_x_kernel<<<dim3(32, 32, C_DIM), dim3(32, 8)>>>(x, p_mask, xth, xtl);

    const dim3 gg(8, 8, C_DIM);
    // Stage 1: b1 = act(Wp_eff @ pset)          [A=Wp shared, B=XT per-ch, triangular]
    gemm_mma<0,1,1,0><<<gg, 256, SMEM>>>(wph, wpl, xth, xtl,
                                         nullptr, nullptr, nullptr, b1h, b1l, nullptr);
    // Stage 2: p = act(b1 @ p_lin_w^T + b)
    gemm_mma<1,0,0,1><<<gg, 256, SMEM>>>(b1h, b1l, plh, pll,
                                         p_lin_b, nullptr, nullptr, ph, pl, nullptr);
    // Transpose p_out for stage 3 (into b1 buffers, now dead)
    transP_kernel<<<dim3(32, 32, C_DIM), dim3(32, 8)>>>(ph, pl, b1h, b1l);
    // Stage 3: z_act = act(Wzp @ p)             [B=p^T per-ch] -> xt buffers (dead)
    gemm_mma<0,1,0,0><<<gg, 256, SMEM>>>(wzh, wzl, b1h, b1l,
                                         nullptr, nullptr, nullptr, xth, xtl, nullptr);
    // Stage 4: out = p + act(z_act @ z_lin_w^T + b)
    gemm_mma<1,0,0,2><<<gg, 256, SMEM>>>(xth, xtl, zlh, zll,
                                         z_lin_b, ph, pl, nullptr, nullptr, out);
}

// round 11
// speedup vs baseline: 2.1506x; 1.0317x over previous
#include <cuda_runtime.h>
#include <cuda_bf16.h>
#include <cstdint>
#include <cstddef>

#define H_DIM 1024
#define I_DIM 1024
#define C_DIM 64

// ---------------------------------------------------------------------------
// Static scratch (module-load allocated; no runtime allocation).
// Explicit 256B alignment — the GEMM uses 16B vector accesses
// (cp.async / uint4) relative to these bases.
// ---------------------------------------------------------------------------
#define ACT_ELEMS ((size_t)C_DIM * H_DIM * I_DIM)   // 64Mi elements
__device__ __align__(256) __nv_bfloat16 g_xth[ACT_ELEMS];   // x*act(pm)^T hi (later z_act)
__device__ __align__(256) __nv_bfloat16 g_xtl[ACT_ELEMS];   // ... lo
__device__ __align__(256) __nv_bfloat16 g_b1h[ACT_ELEMS];   // stage1 out hi (later p_out^T)
__device__ __align__(256) __nv_bfloat16 g_b1l[ACT_ELEMS];
__device__ __align__(256) __nv_bfloat16 g_ph[ACT_ELEMS];    // p_out hi
__device__ __align__(256) __nv_bfloat16 g_pl[ACT_ELEMS];
__device__ __align__(256) __nv_bfloat16 g_wph[H_DIM * H_DIM];
__device__ __align__(256) __nv_bfloat16 g_wpl[H_DIM * H_DIM];
__device__ __align__(256) __nv_bfloat16 g_plh[I_DIM * I_DIM];
__device__ __align__(256) __nv_bfloat16 g_pll[I_DIM * I_DIM];
__device__ __align__(256) __nv_bfloat16 g_wzh[H_DIM * H_DIM];
__device__ __align__(256) __nv_bfloat16 g_wzl[H_DIM * H_DIM];
__device__ __align__(256) __nv_bfloat16 g_zlh[I_DIM * I_DIM];
__device__ __align__(256) __nv_bfloat16 g_zll[I_DIM * I_DIM];

__device__ __forceinline__ float actf(float x) { return fminf(fmaxf(x, -1.0f), 1.0f); }

__device__ __forceinline__ void split_bf16(float v, __nv_bfloat16& hi, __nv_bfloat16& lo) {
    hi = __float2bfloat16(v);
    lo = __float2bfloat16(v - __bfloat162float(hi));
}

// ---------------------------------------------------------------------------
// Elementwise prep kernels
// ---------------------------------------------------------------------------
__global__ void prep_wp_kernel(const float* __restrict__ Wp, const float* __restrict__ Wd,
                               __nv_bfloat16* __restrict__ Oh, __nv_bfloat16* __restrict__ Ol) {
    const int h = blockIdx.x;
    const float dv = Wd[h];
#pragma unroll
    for (int j = 0; j < 4; ++j) {
        const int k = threadIdx.x + j * 256;
        float v = Wp[h * H_DIM + k];
        if (k > h) v = 0.0f;
        else if (k == h) v = fminf(fmaxf(v, 0.0f), 1.0f) + dv;
        __nv_bfloat16 hi, lo; split_bf16(v, hi, lo);
        Oh[h * H_DIM + k] = hi;
        Ol[h * H_DIM + k] = lo;
    }
}

__global__ void conv_mat_kernel(const float* __restrict__ W,
                                __nv_bfloat16* __restrict__ Oh, __nv_bfloat16* __restrict__ Ol) {
    const int i4 = (blockIdx.x * 256 + threadIdx.x) * 4;
    const float4 v = *(const float4*)(W + i4);
    const float vv[4] = {v.x, v.y, v.z, v.w};
    union { uint2 u; __nv_bfloat16 b[4]; } ph, pl;
#pragma unroll
    for (int e = 0; e < 4; ++e) { split_bf16(vv[e], ph.b[e], pl.b[e]); }
    *(uint2*)(Oh + i4) = ph.u;
    *(uint2*)(Ol + i4) = pl.u;
}

// XT[c,i,k] = x[c,k,i] * act(pm[k,i]) -> hi/lo
__global__ void convT_x_kernel(const float* __restrict__ x, const float* __restrict__ pm,
                               __nv_bfloat16* __restrict__ Th, __nv_bfloat16* __restrict__ Tl) {
    __shared__ float t[32][33];
    const int i0 = blockIdx.x * 32, k0 = blockIdx.y * 32;
    const size_t cOff = (size_t)blockIdx.z << 20;
    const int tx = threadIdx.x, ty = threadIdx.y;
#pragma unroll
    for (int r = 0; r < 4; ++r) {
        const int k = k0 + ty + r * 8;
        const float m = actf(pm[(size_t)k * I_DIM + i0 + tx]);
        t[ty + r * 8][tx] = x[cOff + (size_t)k * I_DIM + i0 + tx] * m;
    }
    __syncthreads();
#pragma unroll
    for (int r = 0; r < 4; ++r) {
        const int i = i0 + ty + r * 8;
        const float v = t[tx][ty + r * 8];
        __nv_bfloat16 hi, lo; split_bf16(v, hi, lo);
        Th[cOff + (size_t)i * H_DIM + k0 + tx] = hi;
        Tl[cOff + (size_t)i * H_DIM + k0 + tx] = lo;
    }
}

// PT[c,i,h] = P[c,h,i]  (bf16 hi/lo pair transpose)
__global__ void transP_kernel(const __nv_bfloat16* __restrict__ Ph, const __nv_bfloat16* __restrict__ Pl,
                              __nv_bfloat16* __restrict__ Th, __nv_bfloat16* __restrict__ Tl) {
    __shared__ __nv_bfloat16 th[32][34], tl[32][34];
    const int i0 = blockIdx.x * 32, h0 = blockIdx.y * 32;
    const size_t cOff = (size_t)blockIdx.z << 20;
    const int tx = threadIdx.x, ty = threadIdx.y;
#pragma unroll
    for (int r = 0; r < 4; ++r) {
        const int h = h0 + ty + r * 8;
        th[ty + r * 8][tx] = Ph[cOff + (size_t)h * I_DIM + i0 + tx];
        tl[ty + r * 8][tx] = Pl[cOff + (size_t)h * I_DIM + i0 + tx];
    }
    __syncthreads();
#pragma unroll
    for (int r = 0; r < 4; ++r) {
        const int i = i0 + ty + r * 8;
        Th[cOff + (size_t)i * H_DIM + h0 + tx] = th[tx][ty + r * 8];
        Tl[cOff + (size_t)i * H_DIM + h0 + tx] = tl[tx][ty + r * 8];
    }
}

// ---------------------------------------------------------------------------
// mma.sync / ldmatrix helpers (base ISA, valid on target sm_103)
// ---------------------------------------------------------------------------
__device__ __forceinline__ void mma16816(float* d, const uint32_t* a, const uint32_t* b) {
    asm volatile(
        "mma.sync.aligned.m16n8k16.row.col.f32.bf16.bf16.f32 "
        "{%0,%1,%2,%3}, {%4,%5,%6,%7}, {%8,%9}, {%0,%1,%2,%3};"
        : "+f"(d[0]), "+f"(d[1]), "+f"(d[2]), "+f"(d[3])
        : "r"(a[0]), "r"(a[1]), "r"(a[2]), "r"(a[3]), "r"(b[0]), "r"(b[1]));
}
__device__ __forceinline__ void ldm_x4(uint32_t* r, uint32_t addr) {
    asm volatile("ldmatrix.sync.aligned.m8n8.x4.shared.b16 {%0,%1,%2,%3}, [%4];"
                 : "=r"(r[0]), "=r"(r[1]), "=r"(r[2]), "=r"(r[3]) : "r"(addr));
}
__device__ __forceinline__ void cp16(uint32_t dst, const void* src) {
    asm volatile("cp.async.cg.shared.global [%0], [%1], 16;" :: "r"(dst), "l"(src) : "memory");
}
__device__ __forceinline__ uint32_t smem_u32(const void* p) {
    uint32_t a;
    asm("{ .reg .u64 t; cvta.to.shared.u64 t, %1; cvt.u32.u64 %0, t; }" : "=r"(a) : "l"(p));
    return a;
}

// ---------------------------------------------------------------------------
// GEMM: D[m,n] = sum_k A[m,k]*B[n,k] (both K-contiguous), 3-term bf16 split,
// fp32 accum via mma.sync m16n8k16. Tile 128x128, BK=32, 8 warps (64x32 each),
// 3-buffer cp.async pipeline (1 barrier/chunk). Padded 80B smem rows ->
// conflict-free ldmatrix. Split passes reordered: 16 independent HMMAs
// between accumulator reuses (no same-acc RAW chains).
// APC/BPC: per-channel operand. TRI: triangular k-skip (stage 1).
// EPI: 0 = act -> hi/lo; 1 = act(x+bias) -> hi/lo; 2 = act(x+bias)+res -> f32.
// ---------------------------------------------------------------------------
#define TILE_B 10240        // 128 rows * 80 bytes
#define BUF_B  (4 * TILE_B) // Ah, Al, Bh, Bl
#define NSTAGE 3

template <int APC, int BPC, int TRI, int EPI>
__global__ __launch_bounds__(256, 1)
void gemm_mma(const __nv_bfloat16* __restrict__ Ah, const __nv_bfloat16* __restrict__ Al,
              const __nv_bfloat16* __restrict__ Bh, const __nv_bfloat16* __restrict__ Bl,
              const float* __restrict__ bias,
              const __nv_bfloat16* __restrict__ Rh, const __nv_bfloat16* __restrict__ Rl,
              __nv_bfloat16* __restrict__ Oh, __nv_bfloat16* __restrict__ Ol,
              float* __restrict__ Of)
{
    extern __shared__ char smem[];
    const uint32_t sb = smem_u32(smem);
    const int tid = threadIdx.x;
    const int wid = tid >> 5;
    const int lane = tid & 31;
    const int gID = lane >> 2;      // 0..7
    const int tg  = lane & 3;       // 0..3
    const int warp_m = wid & 1;     // 2 warps over M
    const int warp_n = wid >> 1;    // 4 warps over N
    const int n0 = blockIdx.x * 128;
    const int m0 = blockIdx.y * 128;
    const size_t cOff = (size_t)blockIdx.z << 20;

    const int nch = TRI ? (blockIdx.y + 1) * 4 : 32;   // BK=32 chunks

    const __nv_bfloat16* src[4];
    src[0] = Ah + (APC ? cOff : 0) + (size_t)m0 * 1024;
    src[1] = Al + (APC ? cOff : 0) + (size_t)m0 * 1024;
    src[2] = Bh + (BPC ? cOff : 0) + (size_t)n0 * 1024;
    src[3] = Bl + (BPC ? cOff : 0) + (size_t)n0 * 1024;

    // cp.async issue of one 32-wide K chunk into buffer b (0..2)
    auto issue = [&](int kc, int b) {
#pragma unroll
        for (int t = 0; t < 4; ++t) {
#pragma unroll
            for (int i = 0; i < 2; ++i) {
                const int u = tid + i * 256;        // 0..511 16B units
                const int row = u >> 2;             // 0..127
                const int c16 = u & 3;              // 0..3
                cp16(sb + b * BUF_B + t * TILE_B + row * 80 + c16 * 16,
                     src[t] + (size_t)row * 1024 + kc * 32 + c16 * 8);
            }
        }
        asm volatile("cp.async.commit_group;" ::: "memory");
    };

    // Per-lane ldmatrix base offsets (bytes within a tile buffer).
    // A (m16k16, x4): tiles = (rows+0..7,k0),(rows+8..15,k0),(rows+0..7,k0+8e),(+8,+8e)
    const uint32_t a_off = (uint32_t)((warp_m * 64 + (lane & 7) + ((lane >> 3) & 1) * 8) * 80
                                      + (lane >> 4) * 16);
    // B (two n8k16 frags packed in one x4): tiles = (n+0..7,k0),(n+0..7,k0+8e),(n+8..15,k0),(n+8..15,k0+8e)
    const uint32_t b_off = (uint32_t)((warp_n * 32 + (lane & 7) + ((lane >> 4) & 1) * 8) * 80
                                      + ((lane >> 3) & 1) * 16);

    float acc[4][4][4];
#pragma unroll
    for (int mt = 0; mt < 4; ++mt)
#pragma unroll
        for (int nt = 0; nt < 4; ++nt)
#pragma unroll
            for (int r = 0; r < 4; ++r) acc[mt][nt][r] = 0.0f;

    issue(0, 0);
    issue(1, 1);

    for (int kc = 0; kc < nch; ++kc) {
        if (kc + 1 < nch) {
            asm volatile("cp.async.wait_group 1;" ::: "memory");
        } else {
            asm volatile("cp.async.wait_group 0;" ::: "memory");
        }
        __syncthreads();
        if (kc + 2 < nch) issue(kc + 2, (kc + 2) % NSTAGE);

        const uint32_t bAh = sb + (kc % NSTAGE) * BUF_B;
        const uint32_t bAl = bAh + TILE_B;
        const uint32_t bBh = bAh + 2 * TILE_B;
        const uint32_t bBl = bAh + 3 * TILE_B;

#pragma unroll
        for (int ks = 0; ks < 2; ++ks) {
            const uint32_t ko = ks * 32;
            uint32_t ah[4][4], al[4][4], bhf[4][2], blf[4][2];
#pragma unroll
            for (int mt = 0; mt < 4; ++mt) {
                ldm_x4(ah[mt], bAh + a_off + mt * 1280 + ko);
                ldm_x4(al[mt], bAl + a_off + mt * 1280 + ko);
            }
#pragma unroll
            for (int np = 0; np < 2; ++np) {
                uint32_t t0[4], t1[4];
                ldm_x4(t0, bBh + b_off + np * 1280 + ko);
                bhf[2 * np][0] = t0[0]; bhf[2 * np][1] = t0[1];
                bhf[2 * np + 1][0] = t0[2]; bhf[2 * np + 1][1] = t0[3];
                ldm_x4(t1, bBl + b_off + np * 1280 + ko);
                blf[2 * np][0] = t1[0]; blf[2 * np][1] = t1[1];
                blf[2 * np + 1][0] = t1[2]; blf[2 * np + 1][1] = t1[3];
            }
            // Pass-reordered: 16 independent MMAs per pass, no same-acc chains.
#pragma unroll
            for (int mt = 0; mt < 4; ++mt)
#pragma unroll
                for (int nt = 0; nt < 4; ++nt)
                    mma16816(acc[mt][nt], ah[mt], bhf[nt]);
#pragma unroll
            for (int mt = 0; mt < 4; ++mt)
#pragma unroll
                for (int nt = 0; nt < 4; ++nt)
                    mma16816(acc[mt][nt], ah[mt], blf[nt]);
#pragma unroll
            for (int mt = 0; mt < 4; ++mt)
#pragma unroll
                for (int nt = 0; nt < 4; ++nt)
                    mma16816(acc[mt][nt], al[mt], bhf[nt]);
        }
    }
    __syncthreads();

    // --- Epilogue: stage fp32 tile in smem (pitch 129), then coalesced stores ---
    float* F = (float*)smem;
#pragma unroll
    for (int mt = 0; mt < 4; ++mt)
#pragma unroll
        for (int nt = 0; nt < 4; ++nt)
#pragma unroll
            for (int r = 0; r < 4; ++r) {
                const int rr = warp_m * 64 + mt * 16 + gID + (r >= 2 ? 8 : 0);
                const int cc = warp_n * 32 + nt * 8 + 2 * tg + (r & 1);
                F[rr * 129 + cc] = acc[mt][nt][r];
            }
    __syncthreads();

    {
        const int r  = tid >> 1;
        const int hf = tid & 1;
        const float* Frow = F + r * 129 + hf * 64;
        const size_t ob = cOff + (size_t)(m0 + r) * 1024 + n0 + hf * 64;
        const int jb = n0 + hf * 64;

        float bj[64];
        if (EPI >= 1) {
#pragma unroll
            for (int e4 = 0; e4 < 16; ++e4) {
                const float4 bv = *(const float4*)(bias + jb + e4 * 4);
                bj[e4 * 4 + 0] = bv.x; bj[e4 * 4 + 1] = bv.y;
                bj[e4 * 4 + 2] = bv.z; bj[e4 * 4 + 3] = bv.w;
            }
        }

#pragma unroll
        for (int g = 0; g < 8; ++g) {
            float v[8];
#pragma unroll
            for (int e = 0; e < 8; ++e) {
                float t = Frow[g * 8 + e];
                if (EPI >= 1) t += bj[g * 8 + e];
                v[e] = actf(t);
            }
            if (EPI == 2) {
                union { uint4 u; __nv_bfloat16 b[8]; } rh, rl;
                rh.u = *(const uint4*)(Rh + ob + g * 8);
                rl.u = *(const uint4*)(Rl + ob + g * 8);
                float4 o0, o1;
                o0.x = v[0] + __bfloat162float(rh.b[0]) + __bfloat162float(rl.b[0]);
                o0.y = v[1] + __bfloat162float(rh.b[1]) + __bfloat162float(rl.b[1]);
                o0.z = v[2] + __bfloat162float(rh.b[2]) + __bfloat162float(rl.b[2]);
                o0.w = v[3] + __bfloat162float(rh.b[3]) + __bfloat162float(rl.b[3]);
                o1.x = v[4] + __bfloat162float(rh.b[4]) + __bfloat162float(rl.b[4]);
                o1.y = v[5] + __bfloat162float(rh.b[5]) + __bfloat162float(rl.b[5]);
                o1.z = v[6] + __bfloat162float(rh.b[6]) + __bfloat162float(rl.b[6]);
                o1.w = v[7] + __bfloat162float(rh.b[7]) + __bfloat162float(rl.b[7]);
                *(float4*)(Of + ob + g * 8)     = o0;
                *(float4*)(Of + ob + g * 8 + 4) = o1;
            } else {
                union { uint4 u; __nv_bfloat16 b[8]; } oh_, ol_;
#pragma unroll
                for (int e = 0; e < 8; ++e) split_bf16(v[e], oh_.b[e], ol_.b[e]);
                *(uint4*)(Oh + ob + g * 8) = oh_.u;
                *(uint4*)(Ol + ob + g * 8) = ol_.u;
            }
        }
    }
}

// ---------------------------------------------------------------------------
// Host launcher
// ---------------------------------------------------------------------------
extern "C" void kernel_launch(void* const* d_in, const int* in_sizes, int n_in,
                              void* d_out, int out_size)
{
    (void)in_sizes; (void)n_in; (void)out_size;
    const float* x       = (const float*)d_in[0];
    const float* p_mask  = (const float*)d_in[1];
    const float* Wp      = (const float*)d_in[2];
    const float* Wp_diag = (const float*)d_in[3];
    const float* Wzp     = (const float*)d_in[4];
    const float* p_lin_w = (const float*)d_in[5];
    const float* p_lin_b = (const float*)d_in[6];
    const float* z_lin_w = (const float*)d_in[7];
    const float* z_lin_b = (const float*)d_in[8];
    float* out = (float*)d_out;

    __nv_bfloat16 *xth, *xtl, *b1h, *b1l, *ph, *pl;
    __nv_bfloat16 *wph, *wpl, *plh, *pll, *wzh, *wzl, *zlh, *zll;
    cudaGetSymbolAddress((void**)&xth, g_xth); cudaGetSymbolAddress((void**)&xtl, g_xtl);
    cudaGetSymbolAddress((void**)&b1h, g_b1h); cudaGetSymbolAddress((void**)&b1l, g_b1l);
    cudaGetSymbolAddress((void**)&ph,  g_ph);  cudaGetSymbolAddress((void**)&pl,  g_pl);
    cudaGetSymbolAddress((void**)&wph, g_wph); cudaGetSymbolAddress((void**)&wpl, g_wpl);
    cudaGetSymbolAddress((void**)&plh, g_plh); cudaGetSymbolAddress((void**)&pll, g_pll);
    cudaGetSymbolAddress((void**)&wzh, g_wzh); cudaGetSymbolAddress((void**)&wzl, g_wzl);
    cudaGetSymbolAddress((void**)&zlh, g_zlh); cudaGetSymbolAddress((void**)&zll, g_zll);

    // smem: max(3 pipeline buffers = 122880, epilogue staging 128*129*4 = 66048)
    const int SMEM = NSTAGE * BUF_B;  // 122880
    cudaFuncSetAttribute(gemm_mma<0,1,1,0>, cudaFuncAttributeMaxDynamicSharedMemorySize, SMEM);
    cudaFuncSetAttribute(gemm_mma<1,0,0,1>, cudaFuncAttributeMaxDynamicSharedMemorySize, SMEM);
    cudaFuncSetAttribute(gemm_mma<0,1,0,0>, cudaFuncAttributeMaxDynamicSharedMemorySize, SMEM);
    cudaFuncSetAttribute(gemm_mma<1,0,0,2>, cudaFuncAttributeMaxDynamicSharedMemorySize, SMEM);

    // Prep: weight splits + masked/transposed x
    prep_wp_kernel<<<H_DIM, 256>>>(Wp, Wp_diag, wph, wpl);
    conv_mat_kernel<<<1024, 256>>>(p_lin_w, plh, pll);
    conv_mat_kernel<<<1024, 256>>>(Wzp, wzh, wzl);
    conv_mat_kernel<<<1024, 256>>>(z_lin_w, zlh, zll);
    convT_x_kernel<<<dim3(32, 32, C_DIM), dim3(32, 8)>>>(x, p_mask, xth, xtl);

    const dim3 gg(8, 8, C_DIM);
    // Stage 1: b1 = act(Wp_eff @ pset)          [A=Wp shared, B=XT per-ch, triangular]
    gemm_mma<0,1,1,0><<<gg, 256, SMEM>>>(wph, wpl, xth, xtl,
                                         nullptr, nullptr, nullptr, b1h, b1l, nullptr);
    // Stage 2: p = act(b1 @ p_lin_w^T + b)
    gemm_mma<1,0,0,1><<<gg, 256, SMEM>>>(b1h, b1l, plh, pll,
                                         p_lin_b, nullptr, nullptr, ph, pl, nullptr);
    // Transpose p_out for stage 3 (into b1 buffers, now dead)
    transP_kernel<<<dim3(32, 32, C_DIM), dim3(32, 8)>>>(ph, pl, b1h, b1l);
    // Stage 3: z_act = act(Wzp @ p)             [B=p^T per-ch] -> xt buffers (dead)
    gemm_mma<0,1,0,0><<<gg, 256, SMEM>>>(wzh, wzl, b1h, b1l,
                                         nullptr, nullptr, nullptr, xth, xtl, nullptr);
    // Stage 4: out = p + act(z_act @ z_lin_w^T + b)
    gemm_mma<1,0,0,2><<<gg, 256, SMEM>>>(xth, xtl, zlh, zll,
                                         z_lin_b, ph, pl, nullptr, nullptr, out);
}